// round 3
// baseline (speedup 1.0000x reference)
#include <cuda_runtime.h>
#include <cuda_bf16.h>
#include <cstdint>

#define N_NODES 100000
#define N_EDGES 1600000

// Scratch: two ping-pong node-feature buffers at max D=64. 25.6 MB each.
__device__ float g_bufA[(size_t)N_NODES * 64];
__device__ float g_bufB[(size_t)N_NODES * 64];

__device__ __forceinline__ float* sel_buf(int s) {
    return (s == 0) ? g_bufA : g_bufB;
}

// ---------------------------------------------------------------------------
// Zero a buffer region (float4 stores)
// ---------------------------------------------------------------------------
__global__ void zero_kernel(int sel, int count /* floats, multiple of 4 */) {
    float4* p = reinterpret_cast<float4*>(sel_buf(sel));
    int n4 = count >> 2;
    int i = blockIdx.x * blockDim.x + threadIdx.x;
    if (i < n4) p[i] = make_float4(0.f, 0.f, 0.f, 0.f);
}

// ---------------------------------------------------------------------------
// SpMM: dst[r] += (0.5 * val_e) * src[c]  for each edge e = (r, c)
// One thread per (edge, float4-chunk). D/4 consecutive threads share an edge.
// Scatter via vector reduction red.global.add.v4.f32 (sm_90+).
// ---------------------------------------------------------------------------
template <int D>
__global__ void spmm_kernel(const float* __restrict__ ext_src, int src_sel, int dst_sel,
                            const int* __restrict__ erow,
                            const int* __restrict__ ecol,
                            const float* __restrict__ eval) {
    constexpr int C = D / 4;  // float4 chunks per row (8 or 16, power of 2)
    const float4* __restrict__ src = reinterpret_cast<const float4*>(
        src_sel < 0 ? ext_src : sel_buf(src_sel));
    float* dst = sel_buf(dst_sel);

    long long i = (long long)blockIdx.x * blockDim.x + threadIdx.x;
    long long total = (long long)N_EDGES * C;
    if (i >= total) return;

    int e = (int)(i >> (C == 8 ? 3 : 4));
    int c = (int)(i & (C - 1));

    int r   = erow[e];
    int col = ecol[e];
    float v = 0.5f * eval[e];

    float4 g = __ldg(&src[(long long)col * C + c]);
    float4 o = make_float4(v * g.x, v * g.y, v * g.z, v * g.w);

    float* d = dst + ((long long)r * D + c * 4);
    asm volatile("red.global.add.v4.f32 [%0], {%1, %2, %3, %4};"
                 :: "l"(d), "f"(o.x), "f"(o.y), "f"(o.z), "f"(o.w)
                 : "memory");
}

// ---------------------------------------------------------------------------
// Dense layer: dst[i, :] = act(src[i, :] @ W[DIN, 64] + b)
// Block: 64 x ROWS threads. W staged in shared memory once per block.
// ---------------------------------------------------------------------------
template <int DIN, bool RELU>
__global__ void linear_kernel(int src_sel, int dst_sel, float* ext_dst,
                              const float* __restrict__ W,
                              const float* __restrict__ b) {
    constexpr int ROWS = 4;
    __shared__ float sW[DIN][64];
    __shared__ float sx[ROWS][DIN];

    const float* src = sel_buf(src_sel);
    float* dst = (dst_sel < 0) ? ext_dst : sel_buf(dst_sel);

    int tid = threadIdx.y * 64 + threadIdx.x;  // 0..255
    // Stage W (DIN*64 floats) cooperatively.
    for (int k = tid; k < DIN * 64; k += 256) {
        sW[k / 64][k % 64] = W[k];
    }
    // Stage ROWS input rows.
    int row_base = blockIdx.x * ROWS;
    for (int k = tid; k < ROWS * DIN; k += 256) {
        int rr = k / DIN, kk = k % DIN;
        int row = row_base + rr;
        sx[rr][kk] = (row < N_NODES) ? src[(long long)row * DIN + kk] : 0.f;
    }
    __syncthreads();

    int j = threadIdx.x;           // output feature 0..63
    int rr = threadIdx.y;          // row within block
    int row = row_base + rr;
    if (row >= N_NODES) return;

    float acc = b[j];
#pragma unroll
    for (int k = 0; k < DIN; k++) {
        acc = fmaf(sx[rr][k], sW[k][j], acc);
    }
    if (RELU) acc = fmaxf(acc, 0.f);
    dst[(long long)row * 64 + j] = acc;
}

// ---------------------------------------------------------------------------
// Launch sequence:
//   bufA <- spmm(x)          (D=32)
//   bufB <- spmm(bufA)       (D=32)
//   bufA <- relu(bufB @ W1 + b1)   (D: 32 -> 64)
//   bufB <- spmm(bufA)       (D=64)
//   bufA <- spmm(bufB)       (D=64)
//   out  <- bufA @ W2 + b2
// ---------------------------------------------------------------------------
extern "C" void kernel_launch(void* const* d_in, const int* in_sizes, int n_in,
                              void* d_out, int out_size) {
    const float* x    = (const float*)d_in[0];
    const float* evl  = (const float*)d_in[1];
    const int*   erow = (const int*)  d_in[2];
    const int*   ecol = (const int*)  d_in[3];
    const float* W1   = (const float*)d_in[4];
    const float* b1   = (const float*)d_in[5];
    const float* W2   = (const float*)d_in[6];
    const float* b2   = (const float*)d_in[7];
    float* out = (float*)d_out;

    const int TPB = 256;

    // --- layer 1 propagation (D=32) ---
    {
        int cnt = N_NODES * 32;
        int zb = (cnt / 4 + TPB - 1) / TPB;
        long long work = (long long)N_EDGES * 8;
        int sb = (int)((work + TPB - 1) / TPB);

        zero_kernel<<<zb, TPB>>>(0, cnt);
        spmm_kernel<32><<<sb, TPB>>>(x, -1, 0, erow, ecol, evl);
        zero_kernel<<<zb, TPB>>>(1, cnt);
        spmm_kernel<32><<<sb, TPB>>>(nullptr, 0, 1, erow, ecol, evl);
    }

    // --- layer 1 dense: bufB(D=32) -> bufA(D=64), relu ---
    {
        int blocks = (N_NODES + 3) / 4;
        dim3 blk(64, 4);
        linear_kernel<32, true><<<blocks, blk>>>(1, 0, nullptr, W1, b1);
    }

    // --- layer 2 propagation (D=64) ---
    {
        int cnt = N_NODES * 64;
        int zb = (cnt / 4 + TPB - 1) / TPB;
        long long work = (long long)N_EDGES * 16;
        int sb = (int)((work + TPB - 1) / TPB);

        zero_kernel<<<zb, TPB>>>(1, cnt);
        spmm_kernel<64><<<sb, TPB>>>(nullptr, 0, 1, erow, ecol, evl);
        zero_kernel<<<zb, TPB>>>(0, cnt);
        spmm_kernel<64><<<sb, TPB>>>(nullptr, 1, 0, erow, ecol, evl);
    }

    // --- layer 2 dense: bufA(D=64) -> out ---
    {
        int blocks = (N_NODES + 3) / 4;
        dim3 blk(64, 4);
        linear_kernel<64, false><<<blocks, blk>>>(0, -1, out, W2, b2);
    }
}

// round 4
// speedup vs baseline: 1.2500x; 1.2500x over previous
#include <cuda_runtime.h>
#include <cuda_bf16.h>
#include <cstdint>

#define N_NODES 100000
#define N_EDGES 1600000
#define SCAN_BS 1024
#define SCAN_NB ((N_NODES + SCAN_BS - 1) / SCAN_BS)   // 98

// Ping-pong node-feature buffers (max D=64): 25.6 MB each.
__device__ float g_bufA[(size_t)N_NODES * 64];
__device__ float g_bufB[(size_t)N_NODES * 64];

// CSR scratch (graph is identical for all 4 SpMMs -> build once per launch).
__device__ int    g_deg[N_NODES];
__device__ int    g_rowstart[N_NODES + 1];
__device__ int    g_cursor[N_NODES];
__device__ int    g_bsums[128];
__device__ float2 g_epack[N_EDGES];   // {.x = __int_as_float(col), .y = 0.5f*val}

__device__ __forceinline__ float* sel_buf(int s) {
    return (s == 0) ? g_bufA : g_bufB;
}

// ---------------------------------------------------------------------------
// CSR build
// ---------------------------------------------------------------------------
__global__ void zero_deg_kernel() {
    int i = blockIdx.x * blockDim.x + threadIdx.x;
    if (i < N_NODES) g_deg[i] = 0;
}

__global__ void hist_kernel(const int* __restrict__ erow) {
    int i = blockIdx.x * blockDim.x + threadIdx.x;
    if (i < N_EDGES) atomicAdd(&g_deg[erow[i]], 1);
}

// Per-block inclusive scan (Hillis-Steele over 1024), write exclusive result.
__global__ void scan_local_kernel() {
    __shared__ int s[SCAN_BS];
    int tid = threadIdx.x;
    int idx = blockIdx.x * SCAN_BS + tid;
    int v = (idx < N_NODES) ? g_deg[idx] : 0;
    s[tid] = v;
    __syncthreads();
#pragma unroll
    for (int off = 1; off < SCAN_BS; off <<= 1) {
        int t = (tid >= off) ? s[tid - off] : 0;
        __syncthreads();
        s[tid] += t;
        __syncthreads();
    }
    if (idx < N_NODES) g_rowstart[idx] = s[tid] - v;   // exclusive
    if (tid == SCAN_BS - 1) g_bsums[blockIdx.x] = s[tid];
}

// Single-block exclusive scan of the 98 block sums.
__global__ void scan_bsums_kernel() {
    __shared__ int s[128];
    int tid = threadIdx.x;
    int v = (tid < SCAN_NB) ? g_bsums[tid] : 0;
    s[tid] = v;
    __syncthreads();
#pragma unroll
    for (int off = 1; off < 128; off <<= 1) {
        int t = (tid >= off) ? s[tid - off] : 0;
        __syncthreads();
        s[tid] += t;
        __syncthreads();
    }
    if (tid < SCAN_NB) g_bsums[tid] = s[tid] - v;      // exclusive
}

__global__ void scan_add_kernel() {
    int idx = blockIdx.x * blockDim.x + threadIdx.x;
    if (idx < N_NODES) {
        int r = g_rowstart[idx] + g_bsums[idx >> 10];
        g_rowstart[idx] = r;
        g_cursor[idx] = r;
    }
    if (idx == 0) g_rowstart[N_NODES] = N_EDGES;
}

__global__ void scatter_edges_kernel(const int* __restrict__ erow,
                                     const int* __restrict__ ecol,
                                     const float* __restrict__ eval) {
    int i = blockIdx.x * blockDim.x + threadIdx.x;
    if (i >= N_EDGES) return;
    int r = erow[i];
    int p = atomicAdd(&g_cursor[r], 1);
    float2 pk;
    pk.x = __int_as_float(ecol[i]);
    pk.y = 0.5f * eval[i];
    g_epack[p] = pk;
}

// ---------------------------------------------------------------------------
// Atomic-free SpMM: one warp per destination row.
// Lanes split as SUBS edge-parallel groups x C float4-chunks.
//   D=32: C=8,  SUBS=4      D=64: C=16, SUBS=2
// Register accumulation, shfl-xor reduce across subs, one coalesced row store.
// ---------------------------------------------------------------------------
template <int D>
__global__ void spmm_gather_kernel(const float* __restrict__ ext_src,
                                   int src_sel, int dst_sel) {
    constexpr int C = D / 4;
    constexpr int SUBS = 32 / C;
    const float4* __restrict__ src = reinterpret_cast<const float4*>(
        src_sel < 0 ? ext_src : sel_buf(src_sel));
    float4* dst = reinterpret_cast<float4*>(sel_buf(dst_sel));

    int warp_id = (blockIdx.x * blockDim.x + threadIdx.x) >> 5;
    if (warp_id >= N_NODES) return;
    int lane = threadIdx.x & 31;
    int sub = lane / C;
    int c   = lane % C;

    int start = g_rowstart[warp_id];
    int end   = g_rowstart[warp_id + 1];

    float4 acc = make_float4(0.f, 0.f, 0.f, 0.f);
    for (int e = start + sub; e < end; e += SUBS) {
        float2 ev = __ldg(&g_epack[e]);
        int col = __float_as_int(ev.x);
        float v = ev.y;
        float4 g = __ldg(&src[(size_t)col * C + c]);
        acc.x = fmaf(v, g.x, acc.x);
        acc.y = fmaf(v, g.y, acc.y);
        acc.z = fmaf(v, g.z, acc.z);
        acc.w = fmaf(v, g.w, acc.w);
    }

#pragma unroll
    for (int off = C; off < 32; off <<= 1) {
        acc.x += __shfl_xor_sync(0xFFFFFFFFu, acc.x, off);
        acc.y += __shfl_xor_sync(0xFFFFFFFFu, acc.y, off);
        acc.z += __shfl_xor_sync(0xFFFFFFFFu, acc.z, off);
        acc.w += __shfl_xor_sync(0xFFFFFFFFu, acc.w, off);
    }
    if (sub == 0) dst[(size_t)warp_id * C + c] = acc;
}

// ---------------------------------------------------------------------------
// Dense layer: dst[i, :] = act(src[i, :] @ W[DIN, 64] + b)
// Block: 64 x 16 rows = 1024 threads; W staged once per block (6250 blocks).
// ---------------------------------------------------------------------------
template <int DIN, bool RELU>
__global__ void linear_kernel(int src_sel, float* ext_dst,
                              const float* __restrict__ W,
                              const float* __restrict__ b) {
    constexpr int ROWS = 16;
    __shared__ float sW[DIN][64];
    __shared__ float sx[ROWS][DIN];

    const float* src = sel_buf(src_sel);
    float* dst = (ext_dst != nullptr) ? ext_dst : sel_buf(src_sel == 0 ? 1 : 0);

    int tid = threadIdx.y * 64 + threadIdx.x;  // 0..1023
    for (int k = tid; k < DIN * 64; k += 64 * ROWS) {
        sW[k / 64][k % 64] = W[k];
    }
    int row_base = blockIdx.x * ROWS;
    for (int k = tid; k < ROWS * DIN; k += 64 * ROWS) {
        int rr = k / DIN, kk = k % DIN;
        int row = row_base + rr;
        sx[rr][kk] = (row < N_NODES) ? src[(size_t)row * DIN + kk] : 0.f;
    }
    __syncthreads();

    int j  = threadIdx.x;
    int rr = threadIdx.y;
    int row = row_base + rr;
    if (row >= N_NODES) return;

    float acc = b[j];
#pragma unroll
    for (int k = 0; k < DIN; k++) {
        acc = fmaf(sx[rr][k], sW[k][j], acc);
    }
    if (RELU) acc = fmaxf(acc, 0.f);
    dst[(size_t)row * 64 + j] = acc;
}

// ---------------------------------------------------------------------------
// Launch sequence:
//   CSR build (once; shared by all 4 propagations)
//   bufA <- spmm(x)        (D=32)
//   bufB <- spmm(bufA)     (D=32)
//   bufA <- relu(bufB @ W1 + b1)
//   bufB <- spmm(bufA)     (D=64)
//   bufA <- spmm(bufB)     (D=64)
//   out  <- bufA @ W2 + b2
// ---------------------------------------------------------------------------
extern "C" void kernel_launch(void* const* d_in, const int* in_sizes, int n_in,
                              void* d_out, int out_size) {
    const float* x    = (const float*)d_in[0];
    const float* evl  = (const float*)d_in[1];
    const int*   erow = (const int*)  d_in[2];
    const int*   ecol = (const int*)  d_in[3];
    const float* W1   = (const float*)d_in[4];
    const float* b1   = (const float*)d_in[5];
    const float* W2   = (const float*)d_in[6];
    const float* b2   = (const float*)d_in[7];
    float* out = (float*)d_out;

    const int TPB = 256;
    int node_blocks = (N_NODES + TPB - 1) / TPB;
    int edge_blocks = (N_EDGES + TPB - 1) / TPB;

    // --- CSR build ---
    zero_deg_kernel<<<node_blocks, TPB>>>();
    hist_kernel<<<edge_blocks, TPB>>>(erow);
    scan_local_kernel<<<SCAN_NB, SCAN_BS>>>();
    scan_bsums_kernel<<<1, 128>>>();
    scan_add_kernel<<<node_blocks, TPB>>>();
    scatter_edges_kernel<<<edge_blocks, TPB>>>(erow, ecol, evl);

    // --- SpMM gathers: one warp per row ---
    int gather_blocks = (N_NODES * 32 + TPB - 1) / TPB;   // 12500

    // layer 1 propagation (D=32)
    spmm_gather_kernel<32><<<gather_blocks, TPB>>>(x, -1, 0);
    spmm_gather_kernel<32><<<gather_blocks, TPB>>>(nullptr, 0, 1);

    // layer 1 dense: bufB(32) -> bufA(64), relu
    {
        int blocks = (N_NODES + 15) / 16;
        dim3 blk(64, 16);
        linear_kernel<32, true><<<blocks, blk>>>(1, nullptr, W1, b1);
    }

    // layer 2 propagation (D=64)
    spmm_gather_kernel<64><<<gather_blocks, TPB>>>(nullptr, 0, 1);
    spmm_gather_kernel<64><<<gather_blocks, TPB>>>(nullptr, 1, 0);

    // layer 2 dense: bufA(64) -> out
    {
        int blocks = (N_NODES + 15) / 16;
        dim3 blk(64, 16);
        linear_kernel<64, false><<<blocks, blk>>>(0, out, W2, b2);
    }
}

// round 6
// speedup vs baseline: 1.5126x; 1.2100x over previous
#include <cuda_runtime.h>
#include <cuda_bf16.h>
#include <cstdint>

#define N_NODES 100000
#define N_EDGES 1600000
#define SCAN_BS 1024
#define SCAN_NB ((N_NODES + SCAN_BS - 1) / SCAN_BS)   // 98

// Ping-pong node-feature buffers (max D=64): 25.6 MB each.
__device__ float g_bufA[(size_t)N_NODES * 64];
__device__ float g_bufB[(size_t)N_NODES * 64];

// CSR scratch (graph identical across all 4 SpMMs -> build once per launch).
__device__ int    g_deg[N_NODES];
__device__ int    g_rowstart[N_NODES + 1];
__device__ int    g_cursor[N_NODES];
__device__ int    g_bsums[128];
__device__ float2 g_epack[N_EDGES];   // {.x = __int_as_float(col), .y = 0.5f*val}

__device__ __forceinline__ float* sel_buf(int s) {
    return (s == 0) ? g_bufA : g_bufB;
}

// ---------------------------------------------------------------------------
// CSR build
// ---------------------------------------------------------------------------
__global__ void zero_deg_kernel() {
    int i = blockIdx.x * blockDim.x + threadIdx.x;
    if (i < N_NODES) g_deg[i] = 0;
}

__global__ void hist_kernel(const int* __restrict__ erow) {
    int i = blockIdx.x * blockDim.x + threadIdx.x;
    if (i < N_EDGES) atomicAdd(&g_deg[erow[i]], 1);
}

// Per-block inclusive scan (Hillis-Steele over 1024), write exclusive result.
__global__ void scan_local_kernel() {
    __shared__ int s[SCAN_BS];
    int tid = threadIdx.x;
    int idx = blockIdx.x * SCAN_BS + tid;
    int v = (idx < N_NODES) ? g_deg[idx] : 0;
    s[tid] = v;
    __syncthreads();
#pragma unroll
    for (int off = 1; off < SCAN_BS; off <<= 1) {
        int t = (tid >= off) ? s[tid - off] : 0;
        __syncthreads();
        s[tid] += t;
        __syncthreads();
    }
    if (idx < N_NODES) g_rowstart[idx] = s[tid] - v;   // exclusive
    if (tid == SCAN_BS - 1) g_bsums[blockIdx.x] = s[tid];
}

// Fused: every block redundantly scans the 98 block sums in smem (no grid=1
// kernel), then applies the prefix and initializes cursors.
__global__ void scan_add_kernel() {
    __shared__ int sb[128];
    int tid = threadIdx.x;   // 256 threads
    if (tid < 128) sb[tid] = (tid < SCAN_NB) ? g_bsums[tid] : 0;
    __syncthreads();
#pragma unroll
    for (int off = 1; off < 128; off <<= 1) {
        int t = (tid < 128 && tid >= off) ? sb[tid - off] : 0;
        __syncthreads();
        if (tid < 128) sb[tid] += t;
        __syncthreads();
    }
    // sb is now INCLUSIVE; exclusive prefix for block b is sb[b-1] (0 for b=0).
    int idx = blockIdx.x * blockDim.x + tid;
    if (idx < N_NODES) {
        int blk = idx >> 10;
        int add = (blk == 0) ? 0 : sb[blk - 1];
        int r = g_rowstart[idx] + add;
        g_rowstart[idx] = r;
        g_cursor[idx] = r;
    }
    if (idx == 0) g_rowstart[N_NODES] = N_EDGES;
}

__global__ void scatter_edges_kernel(const int* __restrict__ erow,
                                     const int* __restrict__ ecol,
                                     const float* __restrict__ eval) {
    int i = blockIdx.x * blockDim.x + threadIdx.x;
    if (i >= N_EDGES) return;
    int r = erow[i];
    int p = atomicAdd(&g_cursor[r], 1);
    float2 pk;
    pk.x = __int_as_float(ecol[i]);
    pk.y = 0.5f * eval[i];
    g_epack[p] = pk;
}

// ---------------------------------------------------------------------------
// Warp-level SpMM row reduce: lanes split as SUBS edge groups x C f4-chunks.
// Returns the fully-reduced chunk in lanes with sub==0.
// Mainloop unrolled x2 (dual accumulators) for memory-level parallelism.
// ---------------------------------------------------------------------------
template <int D>
__device__ __forceinline__ float4 spmm_row_reduce(const float4* __restrict__ src,
                                                  int row, int sub, int c) {
    constexpr int C = D / 4;
    constexpr int SUBS = 32 / C;

    int start = g_rowstart[row];
    int end   = g_rowstart[row + 1];

    float4 a0 = make_float4(0.f, 0.f, 0.f, 0.f);
    float4 a1 = make_float4(0.f, 0.f, 0.f, 0.f);
    int e = start + sub;
    for (; e + SUBS < end; e += 2 * SUBS) {
        float2 ev0 = __ldg(&g_epack[e]);
        float2 ev1 = __ldg(&g_epack[e + SUBS]);
        float4 g0 = __ldg(&src[(size_t)__float_as_int(ev0.x) * C + c]);
        float4 g1 = __ldg(&src[(size_t)__float_as_int(ev1.x) * C + c]);
        float v0 = ev0.y, v1 = ev1.y;
        a0.x = fmaf(v0, g0.x, a0.x);  a0.y = fmaf(v0, g0.y, a0.y);
        a0.z = fmaf(v0, g0.z, a0.z);  a0.w = fmaf(v0, g0.w, a0.w);
        a1.x = fmaf(v1, g1.x, a1.x);  a1.y = fmaf(v1, g1.y, a1.y);
        a1.z = fmaf(v1, g1.z, a1.z);  a1.w = fmaf(v1, g1.w, a1.w);
    }
    if (e < end) {
        float2 ev = __ldg(&g_epack[e]);
        float4 g = __ldg(&src[(size_t)__float_as_int(ev.x) * C + c]);
        float v = ev.y;
        a0.x = fmaf(v, g.x, a0.x);  a0.y = fmaf(v, g.y, a0.y);
        a0.z = fmaf(v, g.z, a0.z);  a0.w = fmaf(v, g.w, a0.w);
    }
    a0.x += a1.x; a0.y += a1.y; a0.z += a1.z; a0.w += a1.w;

#pragma unroll
    for (int off = C; off < 32; off <<= 1) {
        a0.x += __shfl_xor_sync(0xFFFFFFFFu, a0.x, off);
        a0.y += __shfl_xor_sync(0xFFFFFFFFu, a0.y, off);
        a0.z += __shfl_xor_sync(0xFFFFFFFFu, a0.z, off);
        a0.w += __shfl_xor_sync(0xFFFFFFFFu, a0.w, off);
    }
    return a0;
}

// ---------------------------------------------------------------------------
// Plain SpMM: one warp per destination row, coalesced f4 row store.
// ---------------------------------------------------------------------------
template <int D>
__global__ void spmm_gather_kernel(const float* __restrict__ ext_src,
                                   int src_sel, int dst_sel) {
    constexpr int C = D / 4;
    const float4* __restrict__ src = reinterpret_cast<const float4*>(
        src_sel < 0 ? ext_src : sel_buf(src_sel));
    float4* dst = reinterpret_cast<float4*>(sel_buf(dst_sel));

    int warp_id = (blockIdx.x * blockDim.x + threadIdx.x) >> 5;
    if (warp_id >= N_NODES) return;
    int lane = threadIdx.x & 31;
    int sub = lane / C, c = lane % C;

    float4 acc = spmm_row_reduce<D>(src, warp_id, sub, c);
    if (sub == 0) dst[(size_t)warp_id * C + c] = acc;
}

// ---------------------------------------------------------------------------
// Fused SpMM + linear epilogue:
//   row = spmm(src)[warp_row]  (DIN values, in-warp)
//   out_row = act(row @ W[DIN,64] + b)   -> dst (64 wide)
// W + b staged in smem once per block; row parked in per-warp smem between
// the reduce and the matmul phase. Each lane produces outputs (2*lane, 2*lane+1).
// ---------------------------------------------------------------------------
template <int DIN, bool RELU>
__global__ void spmm_linear_kernel(int src_sel, float* ext_dst, int dst_sel,
                                   const float* __restrict__ W,
                                   const float* __restrict__ b) {
    constexpr int C = DIN / 4;
    constexpr int WARPS = 8;   // 256 threads
    __shared__ float sW[DIN][64];
    __shared__ float sb[64];
    __shared__ float srow[WARPS][DIN];

    const float4* __restrict__ src =
        reinterpret_cast<const float4*>(sel_buf(src_sel));
    float2* dst = reinterpret_cast<float2*>(
        (ext_dst != nullptr) ? ext_dst : sel_buf(dst_sel));

    int tid = threadIdx.x;
    for (int k = tid; k < DIN * 64; k += 32 * WARPS) sW[k >> 6][k & 63] = W[k];
    if (tid < 64) sb[tid] = b[tid];
    __syncthreads();

    int warp = tid >> 5;
    int lane = tid & 31;
    int row = blockIdx.x * WARPS + warp;
    if (row >= N_NODES) return;

    int sub = lane / C, c = lane % C;
    float4 acc = spmm_row_reduce<DIN>(src, row, sub, c);
    if (sub == 0) {
        reinterpret_cast<float4*>(srow[warp])[c] = acc;
    }
    __syncwarp();

    // Matmul phase: lane computes outputs j0 = 2*lane, j0+1.
    const float2* sW2 = reinterpret_cast<const float2*>(&sW[0][0]);
    float2 o = reinterpret_cast<const float2*>(sb)[lane];
#pragma unroll
    for (int k = 0; k < DIN; k++) {
        float r = srow[warp][k];
        float2 w = sW2[k * 32 + lane];
        o.x = fmaf(r, w.x, o.x);
        o.y = fmaf(r, w.y, o.y);
    }
    if (RELU) {
        o.x = fmaxf(o.x, 0.f);
        o.y = fmaxf(o.y, 0.f);
    }
    dst[(size_t)row * 32 + lane] = o;
}

// ---------------------------------------------------------------------------
// Launch sequence:
//   CSR build (5 kernels, shared by all 4 propagations)
//   bufA <- spmm(x)                          (D=32)
//   bufB <- relu(spmm(bufA) @ W1 + b1)       (fused, 32 -> 64)
//   bufA <- spmm(bufB)                       (D=64)
//   out  <- spmm(bufA) @ W2 + b2             (fused, 64 -> 64)
// ---------------------------------------------------------------------------
extern "C" void kernel_launch(void* const* d_in, const int* in_sizes, int n_in,
                              void* d_out, int out_size) {
    const float* x    = (const float*)d_in[0];
    const float* evl  = (const float*)d_in[1];
    const int*   erow = (const int*)  d_in[2];
    const int*   ecol = (const int*)  d_in[3];
    const float* W1   = (const float*)d_in[4];
    const float* b1   = (const float*)d_in[5];
    const float* W2   = (const float*)d_in[6];
    const float* b2   = (const float*)d_in[7];
    float* out = (float*)d_out;

    const int TPB = 256;
    int node_blocks = (N_NODES + TPB - 1) / TPB;
    int edge_blocks = (N_EDGES + TPB - 1) / TPB;
    int warp_blocks = (N_NODES * 32 + TPB - 1) / TPB;   // warp per row: 12500

    // --- CSR build ---
    zero_deg_kernel<<<node_blocks, TPB>>>();
    hist_kernel<<<edge_blocks, TPB>>>(erow);
    scan_local_kernel<<<SCAN_NB, SCAN_BS>>>();
    scan_add_kernel<<<node_blocks, TPB>>>();
    scatter_edges_kernel<<<edge_blocks, TPB>>>(erow, ecol, evl);

    // --- layer 1 ---
    spmm_gather_kernel<32><<<warp_blocks, TPB>>>(x, -1, 0);
    spmm_linear_kernel<32, true><<<warp_blocks / 1, TPB>>>(0, nullptr, 1, W1, b1);

    // --- layer 2 ---
    spmm_gather_kernel<64><<<warp_blocks, TPB>>>(nullptr, 1, 0);
    spmm_linear_kernel<64, false><<<warp_blocks, TPB>>>(0, out, -1, W2, b2);
}